// round 11
// baseline (speedup 1.0000x reference)
#include <cuda_runtime.h>
#include <cuda.h>
#include <cuda_bf16.h>
#include <stdint.h>

#define N_NODES_C  100000
#define N_GRAPHS_C 128
#define D_NODE 96
#define D_EDGE 32
#define HID 16
#define BN_EPS 1e-5f

#define TILE 256
#define THREADS 256
#define RSTRIDE 52        // fallback kernel row stride
#define PSTR 20           // p row stride (floats)
#define NT 256
#define NSLOT 32          // bin slots per graph (128B stride)

// ---- folded parameters ----
struct CP {
    float W[D_EDGE][HID];     // folded edge-part of W1, [j][k] (k-pairs contiguous)
    float B[HID];
    float W2[HID];
    float b2;
    float pad[3];
    float WxT[D_NODE][HID];   // folded node-part of W1, TRANSPOSED [j][k]
};
__constant__ CP c_par;
__device__   CP g_par;

__device__ float g_p[N_NODES_C * HID];            // 6.4 MB (L2-resident)
__device__ float g_bins[N_GRAPHS_C * NSLOT];      // zero-init; finish re-zeroes

typedef unsigned long long u64;

__device__ __forceinline__ u64 add2(u64 x, u64 y) {
    u64 r; asm("add.rn.f32x2 %0,%1,%2;" : "=l"(r) : "l"(x), "l"(y)); return r;
}

// -------- fold BN into weights --------
__global__ void prep_kernel(const float* __restrict__ W1, const float* __restrict__ b1,
                            const float* __restrict__ gamma, const float* __restrict__ beta,
                            const float* __restrict__ rm, const float* __restrict__ rv,
                            const float* __restrict__ W2, const float* __restrict__ b2) {
    __shared__ float a[HID];
    int lt = threadIdx.x;
    int t  = blockIdx.x * blockDim.x + lt;
    int stride = gridDim.x * blockDim.x;
    if (lt < HID) a[lt] = gamma[lt] * rsqrtf(rv[lt] + BN_EPS);
    __syncthreads();
    for (int i = t; i < D_EDGE * HID; i += stride) {
        int j = i / HID, k = i % HID;
        g_par.W[j][k] = a[k] * W1[k * (D_NODE + D_EDGE) + D_NODE + j];
    }
    for (int i = t; i < D_NODE * HID; i += stride) {
        int j = i / HID, k = i % HID;
        g_par.WxT[j][k] = a[k] * W1[k * (D_NODE + D_EDGE) + j];
    }
    if (t < HID) {
        g_par.B[t]  = a[t] * (b1[t] - rm[t]) + beta[t];
        g_par.W2[t] = W2[t];
    }
    if (t == 0) g_par.b2 = b2[0];
}

// -------- per-node: p[n][k] = WxT[:,k] . x[n], packed pairs --------
__global__ void __launch_bounds__(NT) node_kernel(const float* __restrict__ x, int n_nodes) {
    int n = blockIdx.x * blockDim.x + threadIdx.x;
    if (n >= n_nodes) return;
    u64 A[8];
#pragma unroll
    for (int p = 0; p < 8; p++) A[p] = 0ULL;
    const float4* xr = (const float4*)(x + (size_t)n * D_NODE);
    const u64* cw = (const u64*)&c_par.WxT[0][0];
#pragma unroll
    for (int jj = 0; jj < D_NODE / 4; jj++) {
        float4 v = __ldg(xr + jj);
        float av[4] = {v.x, v.y, v.z, v.w};
#pragma unroll
        for (int i = 0; i < 4; i++) {
            u64 adup;
            asm("mov.b64 %0,{%1,%1};" : "=l"(adup) : "f"(av[i]));
            const u64* wrow = cw + (jj*4 + i) * 8;
#pragma unroll
            for (int p = 0; p < 8; p++)
                asm("fma.rn.f32x2 %0,%1,%2,%0;" : "+l"(A[p]) : "l"(wrow[p]), "l"(adup));
        }
    }
    u64* po = (u64*)(g_p + (size_t)n * HID);
#pragma unroll
    for (int p = 0; p < 8; p += 2)
        *(ulonglong2*)(po + p) = make_ulonglong2(A[p], A[p+1]);
}

// ---- shared epilogue: acc pairs -> msg -> RED ----
__device__ __forceinline__ void mlp_tail_and_red(u64* A, bool v, int g, int lane) {
    if (v) {
        float m = c_par.b2;
#pragma unroll
        for (int p = 0; p < 8; p++) {
            float lo, hi;
            asm("mov.b64 {%0,%1},%2;" : "=f"(lo), "=f"(hi) : "l"(A[p]));
            m = fmaf(c_par.W2[2*p],   fmaxf(lo, 0.0f), m);
            m = fmaf(c_par.W2[2*p+1], fmaxf(hi, 0.0f), m);
        }
        atomicAdd(&g_bins[g * NSLOT + lane], m);
    }
}

// ---- compute one edge from staged buffers (SW128 attr + sP) ----
__device__ __forceinline__ void compute_edge(const float* sAttr, const float* sP,
                                             int t, bool v, int g, int lane) {
    const float* myP = sP + t * PSTR;
    const float* myA = sAttr + t * D_EDGE;
    const int swz = (t & 7);
    const u64* cw = (const u64*)&c_par.W[0][0];
    const u64* cb = (const u64*)&c_par.B[0];
    u64 A[8];
#pragma unroll
    for (int q = 0; q < 2; q++) {
        ulonglong2 p0 = *(const ulonglong2*)(myP + q * 8);
        ulonglong2 p1 = *(const ulonglong2*)(myP + q * 8 + 4);
        A[q*4+0] = add2(p0.x, cb[q*4+0]);
        A[q*4+1] = add2(p0.y, cb[q*4+1]);
        A[q*4+2] = add2(p1.x, cb[q*4+2]);
        A[q*4+3] = add2(p1.y, cb[q*4+3]);
    }
#pragma unroll
    for (int c = 0; c < 8; c++) {
        float4 a4 = *(const float4*)(myA + (c ^ swz) * 4);
        float av[4] = {a4.x, a4.y, a4.z, a4.w};
#pragma unroll
        for (int jj = 0; jj < 4; jj++) {
            u64 adup;
            asm("mov.b64 %0,{%1,%1};" : "=l"(adup) : "f"(av[jj]));
            const u64* wrow = cw + (c*4 + jj) * 8;
#pragma unroll
            for (int p = 0; p < 8; p++)
                asm("fma.rn.f32x2 %0,%1,%2,%0;" : "+l"(A[p]) : "l"(wrow[p]), "l"(adup));
        }
    }
    mlp_tail_and_red(A, v, g, lane);
}

// ================= persistent 2-stage TMA pipeline =================
// floats: attr0[8192] attr1[8192] p0[5120] p1[5120] src0[256] src1[256] mbar[4]
#define SM_ATTR0 0
#define SM_ATTR1 8192
#define SM_P0    16384
#define SM_P1    21504
#define SM_SRC0  26624
#define SM_SRC1  26880
#define SM_MBAR  27136
#define EDGE_SMEM_TMA ((SM_MBAR + 4) * 4)

__global__ void __launch_bounds__(THREADS) edge_kernel_tma(
    const __grid_constant__ CUtensorMap tmap,
    const int* __restrict__ ei,
    const int* __restrict__ batch,
    int n_edges, int n_tiles) {
    extern __shared__ __align__(1024) float sm[];
    float* sAttr[2] = { sm + SM_ATTR0, sm + SM_ATTR1 };
    float* sP[2]    = { sm + SM_P0,    sm + SM_P1 };
    int*   sSrc[2]  = { (int*)(sm + SM_SRC0), (int*)(sm + SM_SRC1) };
    uint32_t mb[2];
    {
        uint32_t base;
        asm("{ .reg .u64 u; cvta.to.shared.u64 u, %1; cvt.u32.u64 %0, u; }"
            : "=r"(base) : "l"(sm));
        mb[0] = base + SM_MBAR * 4;
        mb[1] = base + SM_MBAR * 4 + 8;
    }
    uint32_t attrAddr[2];
#pragma unroll
    for (int s = 0; s < 2; s++) {
        asm("{ .reg .u64 u; cvta.to.shared.u64 u, %1; cvt.u32.u64 %0, u; }"
            : "=r"(attrAddr[s]) : "l"(sAttr[s]));
    }

    const int t    = threadIdx.x;
    const int lane = t & 31;
    const int stride = gridDim.x;

    int ti = blockIdx.x;
    if (t == 0) {
        asm volatile("mbarrier.init.shared.b64 [%0], %1;" :: "r"(mb[0]), "r"(1) : "memory");
        asm volatile("mbarrier.init.shared.b64 [%0], %1;" :: "r"(mb[1]), "r"(1) : "memory");
        asm volatile("fence.proxy.async.shared::cta;" ::: "memory");
    }

    // ---- prologue: produce tile ti into stage 0 ----
    bool v_cur = false; int g_cur = 0;
    if (ti < n_tiles) {
        int e = ti * TILE + t;
        v_cur = e < n_edges;
        int src = 0;
        if (v_cur) {
            src   = __ldg(ei + e);
            g_cur = __ldg(batch + __ldg(ei + n_edges + e));
        }
        sSrc[0][t] = src;
    }
    __syncthreads();          // mbar init + sSrc0 visible
    if (ti < n_tiles) {
        if (t == 0) {
            asm volatile("mbarrier.arrive.expect_tx.shared.b64 _, [%0], %1;"
                         :: "r"(mb[0]), "r"(TILE * D_EDGE * 4) : "memory");
            asm volatile(
                "cp.async.bulk.tensor.2d.shared::cta.global.tile.mbarrier::complete_tx::bytes "
                "[%0], [%1, {%2, %3}], [%4];"
                :: "r"(attrAddr[0]), "l"(&tmap), "r"(0), "r"(ti * TILE), "r"(mb[0]) : "memory");
        }
#pragma unroll
        for (int r = 0; r < 4; r++) {
            int idx = r * THREADS + t;
            int el = idx >> 2, q = idx & 3;
            int s = sSrc[0][el];
            float4 pv = __ldg((const float4*)g_p + (size_t)s * 4 + q);
            *(float4*)(sP[0] + el * PSTR + q * 4) = pv;
        }
    }

    // ---- main loop ----
    int it = 0;
    for (; ti < n_tiles; ti += stride, it++) {
        const int s  = it & 1;
        const int ns = s ^ 1;
        const int nt = ti + stride;
        const bool hn = nt < n_tiles;

        // A: prefetch next tile's indices into regs
        bool vN = false; int gN = 0, srcN = 0;
        if (hn) {
            int en = nt * TILE + t;
            vN = en < n_edges;
            if (vN) {
                srcN = __ldg(ei + en);
                gN   = __ldg(batch + __ldg(ei + n_edges + en));
            }
        }
        __syncthreads();      // B: compute(it-1) done -> buffers[ns] free
        if (hn) {
            sSrc[ns][t] = srcN;
            if (t == 0) {
                asm volatile("mbarrier.arrive.expect_tx.shared.b64 _, [%0], %1;"
                             :: "r"(mb[ns]), "r"(TILE * D_EDGE * 4) : "memory");
                asm volatile(
                    "cp.async.bulk.tensor.2d.shared::cta.global.tile.mbarrier::complete_tx::bytes "
                    "[%0], [%1, {%2, %3}], [%4];"
                    :: "r"(attrAddr[ns]), "l"(&tmap), "r"(0), "r"(nt * TILE), "r"(mb[ns]) : "memory");
            }
        }
        __syncthreads();      // D: sSrc[ns] visible
        if (hn) {
#pragma unroll
            for (int r = 0; r < 4; r++) {
                int idx = r * THREADS + t;
                int el = idx >> 2, q = idx & 3;
                int sv = sSrc[ns][el];
                float4 pv = __ldg((const float4*)g_p + (size_t)sv * 4 + q);
                *(float4*)(sP[ns] + el * PSTR + q * 4) = pv;
            }
        }

        // F: wait TMA for current tile
        {
            const int parity = (it >> 1) & 1;
            asm volatile(
                "{\n\t.reg .pred P1;\n"
                "W%=:\n\tmbarrier.try_wait.parity.acquire.cta.shared::cta.b64 P1, [%0], %1, 0x989680;\n"
                "\t@P1 bra.uni D%=;\n\tbra.uni W%=;\nD%=:\n\t}"
                :: "r"(mb[s]), "r"(parity) : "memory");
        }

        // G: compute + RED
        compute_edge(sAttr[s], sP[s], t, v_cur, g_cur, lane);

        v_cur = vN; g_cur = gN;
    }
}

// ================= fallback edge kernel (R9 path) =================
__global__ void __launch_bounds__(THREADS) edge_kernel_fb(
    const float* __restrict__ edge_attr,
    const int* __restrict__ ei,
    const int* __restrict__ batch,
    int n_edges) {
    extern __shared__ float smf[];
    float* sRow = smf;
    int*   sSrc = (int*)(smf + TILE * RSTRIDE);

    const int t    = threadIdx.x;
    const int lane = t & 31;
    const int e0   = blockIdx.x * TILE;
    const int e    = e0 + t;
    const bool v   = e < n_edges;

    int src = 0, g = 0;
    if (v) {
        src = __ldg(ei + e);
        g   = __ldg(batch + __ldg(ei + n_edges + e));
    }
    sSrc[t] = src;
    __syncthreads();
    {
#pragma unroll
        for (int r = 0; r < (TILE * 4) / THREADS; r++) {
            int idx = r * THREADS + t;
            int el  = idx >> 2;
            int q   = idx & 3;
            int s   = sSrc[el];
            float4 pv = __ldg((const float4*)g_p + (size_t)s * 4 + q);
            *(float4*)(sRow + el * RSTRIDE + D_EDGE + q * 4) = pv;
        }
        const float4* ga = (const float4*)edge_attr;
        const long long base  = (long long)e0 * (D_EDGE / 4);
        const long long total = (long long)n_edges * (D_EDGE / 4);
#pragma unroll
        for (int r = 0; r < (TILE * (D_EDGE / 4)) / THREADS; r++) {
            int idx = r * THREADS + t;
            float4 w = make_float4(0.f, 0.f, 0.f, 0.f);
            if (base + idx < total) w = __ldg(ga + base + idx);
            *(float4*)(sRow + (idx >> 3) * RSTRIDE + (idx & 7) * 4) = w;
        }
    }
    __syncthreads();

    const float* myRow = sRow + t * RSTRIDE;
    const u64* cw = (const u64*)&c_par.W[0][0];
    const u64* cb = (const u64*)&c_par.B[0];
    u64 A[8];
#pragma unroll
    for (int q = 0; q < 2; q++) {
        ulonglong2 p0 = *(const ulonglong2*)(myRow + D_EDGE + q * 8);
        ulonglong2 p1 = *(const ulonglong2*)(myRow + D_EDGE + q * 8 + 4);
        A[q*4+0] = add2(p0.x, cb[q*4+0]);
        A[q*4+1] = add2(p0.y, cb[q*4+1]);
        A[q*4+2] = add2(p1.x, cb[q*4+2]);
        A[q*4+3] = add2(p1.y, cb[q*4+3]);
    }
#pragma unroll
    for (int c = 0; c < 8; c++) {
        float4 a4 = *(const float4*)(myRow + c * 4);
        float av[4] = {a4.x, a4.y, a4.z, a4.w};
#pragma unroll
        for (int jj = 0; jj < 4; jj++) {
            u64 adup;
            asm("mov.b64 %0,{%1,%1};" : "=l"(adup) : "f"(av[jj]));
            const u64* wrow = cw + (c*4 + jj) * 8;
#pragma unroll
            for (int p = 0; p < 8; p++)
                asm("fma.rn.f32x2 %0,%1,%2,%0;" : "+l"(A[p]) : "l"(wrow[p]), "l"(adup));
        }
    }
    mlp_tail_and_red(A, v, g, lane);
}

// -------- finish: one block per graph, warp reduce, write + re-zero --------
__global__ void finish_kernel(float* __restrict__ out) {
    int g = blockIdx.x;
    int lane = threadIdx.x;
    float s = g_bins[g * NSLOT + lane];
    g_bins[g * NSLOT + lane] = 0.0f;
#pragma unroll
    for (int m = 16; m >= 1; m >>= 1) s += __shfl_xor_sync(0xffffffffu, s, m);
    if (lane == 0) out[g] = s;
}

#define EDGE_SMEM_FB (TILE * RSTRIDE * 4 + TILE * 4)

typedef CUresult (*EncodeFn)(CUtensorMap*, CUtensorMapDataType, cuuint32_t, void*,
                             const cuuint64_t*, const cuuint64_t*, const cuuint32_t*,
                             const cuuint32_t*, CUtensorMapInterleave, CUtensorMapSwizzle,
                             CUtensorMapL2promotion, CUtensorMapFloatOOBfill);

extern "C" void kernel_launch(void* const* d_in, const int* in_sizes, int n_in,
                              void* d_out, int out_size) {
    const float* x         = (const float*)d_in[0];
    const float* edge_attr = (const float*)d_in[1];
    const int*   ei        = (const int*)d_in[2];
    const int*   batch     = (const int*)d_in[3];
    const float* W1        = (const float*)d_in[4];
    const float* b1        = (const float*)d_in[5];
    const float* gamma     = (const float*)d_in[6];
    const float* beta      = (const float*)d_in[7];
    const float* rm        = (const float*)d_in[8];
    const float* rv        = (const float*)d_in[9];
    const float* W2        = (const float*)d_in[10];
    const float* b2        = (const float*)d_in[11];
    float* out = (float*)d_out;

    const int n_nodes = in_sizes[0] / D_NODE;
    const int n_edges = in_sizes[1] / D_EDGE;
    const int n_tiles = (n_edges + TILE - 1) / TILE;

    cudaFuncSetAttribute(edge_kernel_tma, cudaFuncAttributeMaxDynamicSharedMemorySize, EDGE_SMEM_TMA);
    cudaFuncSetAttribute(edge_kernel_fb,  cudaFuncAttributeMaxDynamicSharedMemorySize, EDGE_SMEM_FB);

    int n_sm = 148;
    {
        int dev = 0, v = 0;
        if (cudaGetDevice(&dev) == cudaSuccess &&
            cudaDeviceGetAttribute(&v, cudaDevAttrMultiProcessorCount, dev) == cudaSuccess && v > 0)
            n_sm = v;
    }
    int grid_tma = 2 * n_sm;
    if (grid_tma > n_tiles) grid_tma = n_tiles;

    // build tensormap via runtime-resolved driver entry point (no -lcuda)
    bool use_tma = false;
    CUtensorMap tmap;
    {
        void* sym = nullptr;
        cudaDriverEntryPointQueryResult qr;
        if (cudaGetDriverEntryPoint("cuTensorMapEncodeTiled", &sym,
                                    cudaEnableDefault, &qr) == cudaSuccess &&
            qr == cudaDriverEntryPointSuccess && sym) {
            EncodeFn enc = (EncodeFn)sym;
            cuuint64_t dims[2]    = {(cuuint64_t)D_EDGE, (cuuint64_t)n_edges};
            cuuint64_t strides[1] = {(cuuint64_t)D_EDGE * sizeof(float)};
            cuuint32_t box[2]     = {(cuuint32_t)D_EDGE, (cuuint32_t)TILE};
            cuuint32_t estr[2]    = {1, 1};
            CUresult r = enc(&tmap, CU_TENSOR_MAP_DATA_TYPE_FLOAT32, 2,
                             (void*)edge_attr, dims, strides, box, estr,
                             CU_TENSOR_MAP_INTERLEAVE_NONE, CU_TENSOR_MAP_SWIZZLE_128B,
                             CU_TENSOR_MAP_L2_PROMOTION_L2_128B,
                             CU_TENSOR_MAP_FLOAT_OOB_FILL_NONE);
            use_tma = (r == CUDA_SUCCESS);
        }
    }

    void *c_addr = nullptr, *g_addr = nullptr;
    cudaGetSymbolAddress(&c_addr, c_par);
    cudaGetSymbolAddress(&g_addr, g_par);

    prep_kernel<<<8, 256>>>(W1, b1, gamma, beta, rm, rv, W2, b2);
    cudaMemcpyAsync(c_addr, g_addr, sizeof(CP), cudaMemcpyDeviceToDevice, 0);
    node_kernel<<<(n_nodes + NT - 1) / NT, NT>>>(x, n_nodes);
    if (use_tma)
        edge_kernel_tma<<<grid_tma, THREADS, EDGE_SMEM_TMA>>>(tmap, ei, batch, n_edges, n_tiles);
    else
        edge_kernel_fb<<<n_tiles, THREADS, EDGE_SMEM_FB>>>(edge_attr, ei, batch, n_edges);
    finish_kernel<<<N_GRAPHS_C, NSLOT>>>(out);
}

// round 12
// speedup vs baseline: 1.0282x; 1.0282x over previous
#include <cuda_runtime.h>
#include <cuda.h>
#include <cuda_bf16.h>
#include <stdint.h>

#define N_NODES_C  100000
#define N_GRAPHS_C 128
#define D_NODE 96
#define D_EDGE 32
#define HID 16
#define BN_EPS 1e-5f

#define TILE 256
#define THREADS 256
#define RSTRIDE 52        // fallback kernel row stride
#define PSTR 20           // p row stride (floats)
#define NT 256
#define NSLOT 32          // bin slots per graph (128B stride)

// ---- folded parameters ----
struct CP {
    float W[D_EDGE][HID];     // folded edge-part of W1, [j][k] (k-pairs contiguous)
    float B[HID];
    float W2[HID];
    float b2;
    float pad[3];
    float WxT[D_NODE][HID];   // folded node-part of W1, TRANSPOSED [j][k]
};
__constant__ CP c_par;
__device__   CP g_par;

__device__ float g_p[N_NODES_C * HID];            // 6.4 MB (L2-resident)
__device__ float g_bins[N_GRAPHS_C * NSLOT];      // zero-init; finish re-zeroes

typedef unsigned long long u64;

__device__ __forceinline__ u64 add2(u64 x, u64 y) {
    u64 r; asm("add.rn.f32x2 %0,%1,%2;" : "=l"(r) : "l"(x), "l"(y)); return r;
}

// -------- fold BN into weights --------
__global__ void prep_kernel(const float* __restrict__ W1, const float* __restrict__ b1,
                            const float* __restrict__ gamma, const float* __restrict__ beta,
                            const float* __restrict__ rm, const float* __restrict__ rv,
                            const float* __restrict__ W2, const float* __restrict__ b2) {
    __shared__ float a[HID];
    int lt = threadIdx.x;
    int t  = blockIdx.x * blockDim.x + lt;
    int stride = gridDim.x * blockDim.x;
    if (lt < HID) a[lt] = gamma[lt] * rsqrtf(rv[lt] + BN_EPS);
    __syncthreads();
    for (int i = t; i < D_EDGE * HID; i += stride) {
        int j = i / HID, k = i % HID;
        g_par.W[j][k] = a[k] * W1[k * (D_NODE + D_EDGE) + D_NODE + j];
    }
    for (int i = t; i < D_NODE * HID; i += stride) {
        int j = i / HID, k = i % HID;
        g_par.WxT[j][k] = a[k] * W1[k * (D_NODE + D_EDGE) + j];
    }
    if (t < HID) {
        g_par.B[t]  = a[t] * (b1[t] - rm[t]) + beta[t];
        g_par.W2[t] = W2[t];
    }
    if (t == 0) g_par.b2 = b2[0];
}

// -------- per-node: p[n][k] = WxT[:,k] . x[n], packed pairs --------
__global__ void __launch_bounds__(NT) node_kernel(const float* __restrict__ x, int n_nodes) {
    int n = blockIdx.x * blockDim.x + threadIdx.x;
    if (n >= n_nodes) return;
    u64 A[8];
#pragma unroll
    for (int p = 0; p < 8; p++) A[p] = 0ULL;
    const float4* xr = (const float4*)(x + (size_t)n * D_NODE);
    const u64* cw = (const u64*)&c_par.WxT[0][0];
#pragma unroll
    for (int jj = 0; jj < D_NODE / 4; jj++) {
        float4 v = __ldg(xr + jj);
        float av[4] = {v.x, v.y, v.z, v.w};
#pragma unroll
        for (int i = 0; i < 4; i++) {
            u64 adup;
            asm("mov.b64 %0,{%1,%1};" : "=l"(adup) : "f"(av[i]));
            const u64* wrow = cw + (jj*4 + i) * 8;
#pragma unroll
            for (int p = 0; p < 8; p++)
                asm("fma.rn.f32x2 %0,%1,%2,%0;" : "+l"(A[p]) : "l"(wrow[p]), "l"(adup));
        }
    }
    u64* po = (u64*)(g_p + (size_t)n * HID);
#pragma unroll
    for (int p = 0; p < 8; p += 2)
        *(ulonglong2*)(po + p) = make_ulonglong2(A[p], A[p+1]);
}

// ---- epilogue: acc pairs -> msg -> RED ----
__device__ __forceinline__ void mlp_tail_and_red(u64* A, bool v, int g, int lane) {
    if (v) {
        float m = c_par.b2;
#pragma unroll
        for (int p = 0; p < 8; p++) {
            float lo, hi;
            asm("mov.b64 {%0,%1},%2;" : "=f"(lo), "=f"(hi) : "l"(A[p]));
            m = fmaf(c_par.W2[2*p],   fmaxf(lo, 0.0f), m);
            m = fmaf(c_par.W2[2*p+1], fmaxf(hi, 0.0f), m);
        }
        atomicAdd(&g_bins[g * NSLOT + lane], m);
    }
}

// ================= TMA edge kernel: 2 tiles per block, fused compute =================
// floats: attr0[8192] attr1[8192] p0[5120] p1[5120] src0[256] src1[256] mbar[4]
#define SM_ATTR0 0
#define SM_ATTR1 8192
#define SM_P0    16384
#define SM_P1    21504
#define SM_SRC0  26624
#define SM_SRC1  26880
#define SM_MBAR  27136
#define EDGE_SMEM_TMA ((SM_MBAR + 4) * 4)

__global__ void __launch_bounds__(THREADS) edge_kernel_tma(
    const __grid_constant__ CUtensorMap tmap,
    const int* __restrict__ ei,
    const int* __restrict__ batch,
    int n_edges, int n_tiles) {
    extern __shared__ __align__(1024) float sm[];
    float* sAttr0 = sm + SM_ATTR0;
    float* sAttr1 = sm + SM_ATTR1;
    float* sP0    = sm + SM_P0;
    float* sP1    = sm + SM_P1;
    int*   sSrc0  = (int*)(sm + SM_SRC0);
    int*   sSrc1  = (int*)(sm + SM_SRC1);
    uint32_t smbase;
    asm("{ .reg .u64 u; cvta.to.shared.u64 u, %1; cvt.u32.u64 %0, u; }"
        : "=r"(smbase) : "l"(sm));
    const uint32_t mb0 = smbase + SM_MBAR * 4;
    const uint32_t mb1 = smbase + SM_MBAR * 4 + 8;
    const uint32_t at0 = smbase + SM_ATTR0 * 4;
    const uint32_t at1 = smbase + SM_ATTR1 * 4;

    const int t    = threadIdx.x;
    const int lane = t & 31;
    const int ti0  = blockIdx.x * 2;
    const int ti1  = ti0 + 1;
    const bool h1  = ti1 < n_tiles;

    // issue both TMAs as early as possible (t0 does init+fence+expect+issue in program order)
    if (t == 0) {
        asm volatile("mbarrier.init.shared.b64 [%0], %1;" :: "r"(mb0), "r"(1) : "memory");
        asm volatile("mbarrier.init.shared.b64 [%0], %1;" :: "r"(mb1), "r"(1) : "memory");
        asm volatile("fence.proxy.async.shared::cta;" ::: "memory");
        asm volatile("mbarrier.arrive.expect_tx.shared.b64 _, [%0], %1;"
                     :: "r"(mb0), "r"(TILE * D_EDGE * 4) : "memory");
        asm volatile(
            "cp.async.bulk.tensor.2d.shared::cta.global.tile.mbarrier::complete_tx::bytes "
            "[%0], [%1, {%2, %3}], [%4];"
            :: "r"(at0), "l"(&tmap), "r"(0), "r"(ti0 * TILE), "r"(mb0) : "memory");
        if (h1) {
            asm volatile("mbarrier.arrive.expect_tx.shared.b64 _, [%0], %1;"
                         :: "r"(mb1), "r"(TILE * D_EDGE * 4) : "memory");
            asm volatile(
                "cp.async.bulk.tensor.2d.shared::cta.global.tile.mbarrier::complete_tx::bytes "
                "[%0], [%1, {%2, %3}], [%4];"
                :: "r"(at1), "l"(&tmap), "r"(0), "r"(ti1 * TILE), "r"(mb1) : "memory");
        }
    }

    // per-thread edge metadata for both tiles
    const int e0 = ti0 * TILE + t;
    const int e1 = ti1 * TILE + t;
    const bool v0 = e0 < n_edges;
    const bool v1 = h1 && (e1 < n_edges);
    int s0 = 0, g0 = 0, s1 = 0, g1 = 0;
    if (v0) { s0 = __ldg(ei + e0); g0 = __ldg(batch + __ldg(ei + n_edges + e0)); }
    if (v1) { s1 = __ldg(ei + e1); g1 = __ldg(batch + __ldg(ei + n_edges + e1)); }
    sSrc0[t] = s0;
    sSrc1[t] = s1;
    __syncthreads();                     // sSrc + mbar init visible

    // cooperative p-gathers for both tiles (under the in-flight TMAs)
#pragma unroll
    for (int r = 0; r < 4; r++) {
        int idx = r * THREADS + t;
        int el = idx >> 2, q = idx & 3;
        int sv = sSrc0[el];
        float4 pv = __ldg((const float4*)g_p + (size_t)sv * 4 + q);
        *(float4*)(sP0 + el * PSTR + q * 4) = pv;
    }
    if (h1) {
#pragma unroll
        for (int r = 0; r < 4; r++) {
            int idx = r * THREADS + t;
            int el = idx >> 2, q = idx & 3;
            int sv = sSrc1[el];
            float4 pv = __ldg((const float4*)g_p + (size_t)sv * 4 + q);
            *(float4*)(sP1 + el * PSTR + q * 4) = pv;
        }
    }
    __syncthreads();                     // sP ready

    // wait both TMAs (single-use, parity 0)
    asm volatile(
        "{\n\t.reg .pred P1;\n"
        "W%=:\n\tmbarrier.try_wait.parity.acquire.cta.shared::cta.b64 P1, [%0], %1, 0x989680;\n"
        "\t@P1 bra.uni D%=;\n\tbra.uni W%=;\nD%=:\n\t}"
        :: "r"(mb0), "r"(0) : "memory");
    if (h1) {
        asm volatile(
            "{\n\t.reg .pred P1;\n"
            "W%=:\n\tmbarrier.try_wait.parity.acquire.cta.shared::cta.b64 P1, [%0], %1, 0x989680;\n"
            "\t@P1 bra.uni D%=;\n\tbra.uni W%=;\nD%=:\n\t}"
            :: "r"(mb1), "r"(0) : "memory");
    }

    // fused compute: both edges share every weight load
    const float* myP0 = sP0 + t * PSTR;
    const float* myP1 = sP1 + t * PSTR;
    const float* myA0 = sAttr0 + t * D_EDGE;
    const float* myA1 = sAttr1 + t * D_EDGE;
    const int swz = (t & 7);
    const u64* cw = (const u64*)&c_par.W[0][0];
    const u64* cb = (const u64*)&c_par.B[0];

    u64 A[8], Bv[8];
#pragma unroll
    for (int q = 0; q < 2; q++) {
        ulonglong2 a0 = *(const ulonglong2*)(myP0 + q * 8);
        ulonglong2 a1 = *(const ulonglong2*)(myP0 + q * 8 + 4);
        A[q*4+0] = add2(a0.x, cb[q*4+0]);
        A[q*4+1] = add2(a0.y, cb[q*4+1]);
        A[q*4+2] = add2(a1.x, cb[q*4+2]);
        A[q*4+3] = add2(a1.y, cb[q*4+3]);
        ulonglong2 b0 = *(const ulonglong2*)(myP1 + q * 8);
        ulonglong2 b1 = *(const ulonglong2*)(myP1 + q * 8 + 4);
        Bv[q*4+0] = add2(b0.x, cb[q*4+0]);
        Bv[q*4+1] = add2(b0.y, cb[q*4+1]);
        Bv[q*4+2] = add2(b1.x, cb[q*4+2]);
        Bv[q*4+3] = add2(b1.y, cb[q*4+3]);
    }
#pragma unroll
    for (int c = 0; c < 8; c++) {
        float4 a4 = *(const float4*)(myA0 + (c ^ swz) * 4);
        float4 b4 = *(const float4*)(myA1 + (c ^ swz) * 4);
        float avA[4] = {a4.x, a4.y, a4.z, a4.w};
        float avB[4] = {b4.x, b4.y, b4.z, b4.w};
#pragma unroll
        for (int jj = 0; jj < 4; jj++) {
            u64 dupA, dupB;
            asm("mov.b64 %0,{%1,%1};" : "=l"(dupA) : "f"(avA[jj]));
            asm("mov.b64 %0,{%1,%1};" : "=l"(dupB) : "f"(avB[jj]));
            const u64* wrow = cw + (c*4 + jj) * 8;
#pragma unroll
            for (int p = 0; p < 8; p++) {
                u64 w = wrow[p];
                asm("fma.rn.f32x2 %0,%1,%2,%0;" : "+l"(A[p])  : "l"(w), "l"(dupA));
                asm("fma.rn.f32x2 %0,%1,%2,%0;" : "+l"(Bv[p]) : "l"(w), "l"(dupB));
            }
        }
    }
    mlp_tail_and_red(A,  v0, g0, lane);
    mlp_tail_and_red(Bv, v1, g1, lane);
}

// ================= fallback edge kernel (R9 path) =================
__global__ void __launch_bounds__(THREADS) edge_kernel_fb(
    const float* __restrict__ edge_attr,
    const int* __restrict__ ei,
    const int* __restrict__ batch,
    int n_edges) {
    extern __shared__ float smf[];
    float* sRow = smf;
    int*   sSrc = (int*)(smf + TILE * RSTRIDE);

    const int t    = threadIdx.x;
    const int lane = t & 31;
    const int e0   = blockIdx.x * TILE;
    const int e    = e0 + t;
    const bool v   = e < n_edges;

    int src = 0, g = 0;
    if (v) {
        src = __ldg(ei + e);
        g   = __ldg(batch + __ldg(ei + n_edges + e));
    }
    sSrc[t] = src;
    __syncthreads();
    {
#pragma unroll
        for (int r = 0; r < (TILE * 4) / THREADS; r++) {
            int idx = r * THREADS + t;
            int el  = idx >> 2;
            int q   = idx & 3;
            int s   = sSrc[el];
            float4 pv = __ldg((const float4*)g_p + (size_t)s * 4 + q);
            *(float4*)(sRow + el * RSTRIDE + D_EDGE + q * 4) = pv;
        }
        const float4* ga = (const float4*)edge_attr;
        const long long base  = (long long)e0 * (D_EDGE / 4);
        const long long total = (long long)n_edges * (D_EDGE / 4);
#pragma unroll
        for (int r = 0; r < (TILE * (D_EDGE / 4)) / THREADS; r++) {
            int idx = r * THREADS + t;
            float4 w = make_float4(0.f, 0.f, 0.f, 0.f);
            if (base + idx < total) w = __ldg(ga + base + idx);
            *(float4*)(sRow + (idx >> 3) * RSTRIDE + (idx & 7) * 4) = w;
        }
    }
    __syncthreads();

    const float* myRow = sRow + t * RSTRIDE;
    const u64* cw = (const u64*)&c_par.W[0][0];
    const u64* cb = (const u64*)&c_par.B[0];
    u64 A[8];
#pragma unroll
    for (int q = 0; q < 2; q++) {
        ulonglong2 p0 = *(const ulonglong2*)(myRow + D_EDGE + q * 8);
        ulonglong2 p1 = *(const ulonglong2*)(myRow + D_EDGE + q * 8 + 4);
        A[q*4+0] = add2(p0.x, cb[q*4+0]);
        A[q*4+1] = add2(p0.y, cb[q*4+1]);
        A[q*4+2] = add2(p1.x, cb[q*4+2]);
        A[q*4+3] = add2(p1.y, cb[q*4+3]);
    }
#pragma unroll
    for (int c = 0; c < 8; c++) {
        float4 a4 = *(const float4*)(myRow + c * 4);
        float av[4] = {a4.x, a4.y, a4.z, a4.w};
#pragma unroll
        for (int jj = 0; jj < 4; jj++) {
            u64 adup;
            asm("mov.b64 %0,{%1,%1};" : "=l"(adup) : "f"(av[jj]));
            const u64* wrow = cw + (c*4 + jj) * 8;
#pragma unroll
            for (int p = 0; p < 8; p++)
                asm("fma.rn.f32x2 %0,%1,%2,%0;" : "+l"(A[p]) : "l"(wrow[p]), "l"(adup));
        }
    }
    mlp_tail_and_red(A, v, g, lane);
}

// -------- finish: one block per graph, warp reduce, write + re-zero --------
__global__ void finish_kernel(float* __restrict__ out) {
    int g = blockIdx.x;
    int lane = threadIdx.x;
    float s = g_bins[g * NSLOT + lane];
    g_bins[g * NSLOT + lane] = 0.0f;
#pragma unroll
    for (int m = 16; m >= 1; m >>= 1) s += __shfl_xor_sync(0xffffffffu, s, m);
    if (lane == 0) out[g] = s;
}

#define EDGE_SMEM_FB (TILE * RSTRIDE * 4 + TILE * 4)

typedef CUresult (*EncodeFn)(CUtensorMap*, CUtensorMapDataType, cuuint32_t, void*,
                             const cuuint64_t*, const cuuint64_t*, const cuuint32_t*,
                             const cuuint32_t*, CUtensorMapInterleave, CUtensorMapSwizzle,
                             CUtensorMapL2promotion, CUtensorMapFloatOOBfill);

extern "C" void kernel_launch(void* const* d_in, const int* in_sizes, int n_in,
                              void* d_out, int out_size) {
    const float* x         = (const float*)d_in[0];
    const float* edge_attr = (const float*)d_in[1];
    const int*   ei        = (const int*)d_in[2];
    const int*   batch     = (const int*)d_in[3];
    const float* W1        = (const float*)d_in[4];
    const float* b1        = (const float*)d_in[5];
    const float* gamma     = (const float*)d_in[6];
    const float* beta      = (const float*)d_in[7];
    const float* rm        = (const float*)d_in[8];
    const float* rv        = (const float*)d_in[9];
    const float* W2        = (const float*)d_in[10];
    const float* b2        = (const float*)d_in[11];
    float* out = (float*)d_out;

    const int n_nodes = in_sizes[0] / D_NODE;
    const int n_edges = in_sizes[1] / D_EDGE;
    const int n_tiles = (n_edges + TILE - 1) / TILE;
    const int n_blk2  = (n_tiles + 1) / 2;

    cudaFuncSetAttribute(edge_kernel_tma, cudaFuncAttributeMaxDynamicSharedMemorySize, EDGE_SMEM_TMA);
    cudaFuncSetAttribute(edge_kernel_fb,  cudaFuncAttributeMaxDynamicSharedMemorySize, EDGE_SMEM_FB);

    // build tensormap via runtime-resolved driver entry point (no -lcuda)
    bool use_tma = false;
    CUtensorMap tmap;
    {
        void* sym = nullptr;
        cudaDriverEntryPointQueryResult qr;
        if (cudaGetDriverEntryPoint("cuTensorMapEncodeTiled", &sym,
                                    cudaEnableDefault, &qr) == cudaSuccess &&
            qr == cudaDriverEntryPointSuccess && sym) {
            EncodeFn enc = (EncodeFn)sym;
            cuuint64_t dims[2]    = {(cuuint64_t)D_EDGE, (cuuint64_t)n_edges};
            cuuint64_t strides[1] = {(cuuint64_t)D_EDGE * sizeof(float)};
            cuuint32_t box[2]     = {(cuuint32_t)D_EDGE, (cuuint32_t)TILE};
            cuuint32_t estr[2]    = {1, 1};
            CUresult r = enc(&tmap, CU_TENSOR_MAP_DATA_TYPE_FLOAT32, 2,
                             (void*)edge_attr, dims, strides, box, estr,
                             CU_TENSOR_MAP_INTERLEAVE_NONE, CU_TENSOR_MAP_SWIZZLE_128B,
                             CU_TENSOR_MAP_L2_PROMOTION_L2_128B,
                             CU_TENSOR_MAP_FLOAT_OOB_FILL_NONE);
            use_tma = (r == CUDA_SUCCESS);
        }
    }

    void *c_addr = nullptr, *g_addr = nullptr;
    cudaGetSymbolAddress(&c_addr, c_par);
    cudaGetSymbolAddress(&g_addr, g_par);

    prep_kernel<<<8, 256>>>(W1, b1, gamma, beta, rm, rv, W2, b2);
    cudaMemcpyAsync(c_addr, g_addr, sizeof(CP), cudaMemcpyDeviceToDevice, 0);
    node_kernel<<<(n_nodes + NT - 1) / NT, NT>>>(x, n_nodes);
    if (use_tma)
        edge_kernel_tma<<<n_blk2, THREADS, EDGE_SMEM_TMA>>>(tmap, ei, batch, n_edges, n_tiles);
    else
        edge_kernel_fb<<<n_tiles, THREADS, EDGE_SMEM_FB>>>(edge_attr, ei, batch, n_edges);
    finish_kernel<<<N_GRAPHS_C, NSLOT>>>(out);
}

// round 13
// speedup vs baseline: 1.0995x; 1.0694x over previous
#include <cuda_runtime.h>
#include <cuda.h>
#include <cuda_bf16.h>
#include <stdint.h>

#define N_NODES_C  100000
#define N_GRAPHS_C 128
#define D_NODE 96
#define D_EDGE 32
#define HID 16
#define BN_EPS 1e-5f

#define TILE 128          // edges per block (smaller -> 8 blocks/SM)
#define THREADS 128
#define RSTRIDE 52        // fallback kernel row stride
#define PSTR 20           // p row stride (floats)
#define NT 256
#define NSLOT 32          // bin slots per graph (128B stride)

// ---- folded parameters ----
struct CP {
    float W[D_EDGE][HID];     // folded edge-part of W1, [j][k] (k-pairs contiguous)
    float B[HID];
    float W2[HID];
    float b2;
    float pad[3];
    float WxT[D_NODE][HID];   // folded node-part of W1, TRANSPOSED [j][k]
};
__constant__ CP c_par;
__device__   CP g_par;

__device__ float g_p[N_NODES_C * HID];            // 6.4 MB (L2-resident)
__device__ float g_bins[N_GRAPHS_C * NSLOT];      // zero-init; finisher re-zeroes
__device__ unsigned g_done = 0;                   // completion counter; reset by finisher

typedef unsigned long long u64;

__device__ __forceinline__ u64 add2(u64 x, u64 y) {
    u64 r; asm("add.rn.f32x2 %0,%1,%2;" : "=l"(r) : "l"(x), "l"(y)); return r;
}

// -------- fold BN into weights --------
__global__ void prep_kernel(const float* __restrict__ W1, const float* __restrict__ b1,
                            const float* __restrict__ gamma, const float* __restrict__ beta,
                            const float* __restrict__ rm, const float* __restrict__ rv,
                            const float* __restrict__ W2, const float* __restrict__ b2) {
    __shared__ float a[HID];
    int lt = threadIdx.x;
    int t  = blockIdx.x * blockDim.x + lt;
    int stride = gridDim.x * blockDim.x;
    if (lt < HID) a[lt] = gamma[lt] * rsqrtf(rv[lt] + BN_EPS);
    __syncthreads();
    for (int i = t; i < D_EDGE * HID; i += stride) {
        int j = i / HID, k = i % HID;
        g_par.W[j][k] = a[k] * W1[k * (D_NODE + D_EDGE) + D_NODE + j];
    }
    for (int i = t; i < D_NODE * HID; i += stride) {
        int j = i / HID, k = i % HID;
        g_par.WxT[j][k] = a[k] * W1[k * (D_NODE + D_EDGE) + j];
    }
    if (t < HID) {
        g_par.B[t]  = a[t] * (b1[t] - rm[t]) + beta[t];
        g_par.W2[t] = W2[t];
    }
    if (t == 0) g_par.b2 = b2[0];
}

// -------- per-node: p[n][k] = WxT[:,k] . x[n], packed pairs --------
__global__ void __launch_bounds__(NT) node_kernel(const float* __restrict__ x, int n_nodes) {
    int n = blockIdx.x * blockDim.x + threadIdx.x;
    if (n >= n_nodes) return;
    u64 A[8];
#pragma unroll
    for (int p = 0; p < 8; p++) A[p] = 0ULL;
    const float4* xr = (const float4*)(x + (size_t)n * D_NODE);
    const u64* cw = (const u64*)&c_par.WxT[0][0];
#pragma unroll
    for (int jj = 0; jj < D_NODE / 4; jj++) {
        float4 v = __ldg(xr + jj);
        float av[4] = {v.x, v.y, v.z, v.w};
#pragma unroll
        for (int i = 0; i < 4; i++) {
            u64 adup;
            asm("mov.b64 %0,{%1,%1};" : "=l"(adup) : "f"(av[i]));
            const u64* wrow = cw + (jj*4 + i) * 8;
#pragma unroll
            for (int p = 0; p < 8; p++)
                asm("fma.rn.f32x2 %0,%1,%2,%0;" : "+l"(A[p]) : "l"(wrow[p]), "l"(adup));
        }
    }
    u64* po = (u64*)(g_p + (size_t)n * HID);
#pragma unroll
    for (int p = 0; p < 8; p += 2)
        *(ulonglong2*)(po + p) = make_ulonglong2(A[p], A[p+1]);
}

// ---- epilogue: acc pairs -> msg -> RED ----
__device__ __forceinline__ void mlp_tail_and_red(u64* A, bool v, int g, int lane) {
    if (v) {
        float m = c_par.b2;
#pragma unroll
        for (int p = 0; p < 8; p++) {
            float lo, hi;
            asm("mov.b64 {%0,%1},%2;" : "=f"(lo), "=f"(hi) : "l"(A[p]));
            m = fmaf(c_par.W2[2*p],   fmaxf(lo, 0.0f), m);
            m = fmaf(c_par.W2[2*p+1], fmaxf(hi, 0.0f), m);
        }
        atomicAdd(&g_bins[g * NSLOT + lane], m);
    }
}

// ================= TMA edge kernel (R10 structure, TILE=128) =================
// floats: attr[4096] p[2560] src[128] mbar[4]
#define SM_ATTR 0
#define SM_P    4096
#define SM_SRC  (SM_P + TILE * PSTR)        // 6656
#define SM_MBAR (SM_SRC + TILE)             // 6784 (8B aligned)
#define EDGE_SMEM_TMA ((SM_MBAR + 4) * 4)   // 27152 B

__global__ void __launch_bounds__(THREADS) edge_kernel_tma(
    const __grid_constant__ CUtensorMap tmap,
    const int* __restrict__ ei,
    const int* __restrict__ batch,
    float* __restrict__ out,
    int n_edges, int n_tiles) {
    extern __shared__ __align__(1024) float sm[];
    float* sAttr = sm + SM_ATTR;
    float* sP    = sm + SM_P;
    int*   sSrc  = (int*)(sm + SM_SRC);
    uint32_t mbar;
    {
        uint32_t base;
        asm("{ .reg .u64 u; cvta.to.shared.u64 u, %1; cvt.u32.u64 %0, u; }"
            : "=r"(base) : "l"(sm));
        mbar = base + SM_MBAR * 4;
    }

    const int t    = threadIdx.x;
    const int lane = t & 31;
    const int e0   = blockIdx.x * TILE;
    const int e    = e0 + t;
    const bool v   = e < n_edges;

    int src = 0, g = 0;
    if (v) {
        src = __ldg(ei + e);
        g   = __ldg(batch + __ldg(ei + n_edges + e));
    }
    sSrc[t] = src;
    __syncthreads();

    if (t == 0) {
        asm volatile("mbarrier.init.shared.b64 [%0], %1;" :: "r"(mbar), "r"(1) : "memory");
        asm volatile("fence.proxy.async.shared::cta;" ::: "memory");
        asm volatile("mbarrier.arrive.expect_tx.shared.b64 _, [%0], %1;"
                     :: "r"(mbar), "r"(TILE * D_EDGE * 4) : "memory");
        uint32_t dst;
        asm("{ .reg .u64 u; cvta.to.shared.u64 u, %1; cvt.u32.u64 %0, u; }"
            : "=r"(dst) : "l"(sAttr));
        asm volatile(
            "cp.async.bulk.tensor.2d.shared::cta.global.tile.mbarrier::complete_tx::bytes "
            "[%0], [%1, {%2, %3}], [%4];"
            :: "r"(dst), "l"(&tmap), "r"(0), "r"(e0), "r"(mbar) : "memory");
    }

    // cooperative p gather under the TMA stream
#pragma unroll
    for (int r = 0; r < (TILE * 4) / THREADS; r++) {
        int idx = r * THREADS + t;
        int el  = idx >> 2;
        int q   = idx & 3;
        int s   = sSrc[el];
        float4 pv = __ldg((const float4*)g_p + (size_t)s * 4 + q);
        *(float4*)(sP + el * PSTR + q * 4) = pv;
    }
    __syncthreads();   // sP ready; mbar init visible

    // wait for TMA (parity 0, single use)
    asm volatile(
        "{\n\t.reg .pred P1;\n"
        "W%=:\n\tmbarrier.try_wait.parity.acquire.cta.shared::cta.b64 P1, [%0], %1, 0x989680;\n"
        "\t@P1 bra.uni D%=;\n\tbra.uni W%=;\nD%=:\n\t}"
        :: "r"(mbar), "r"(0) : "memory");

    const float* myP = sP + t * PSTR;
    const float* myA = sAttr + t * D_EDGE;     // swizzled row
    const int swz = (t & 7);
    const u64* cw = (const u64*)&c_par.W[0][0];
    const u64* cb = (const u64*)&c_par.B[0];

    u64 A[8];
#pragma unroll
    for (int q = 0; q < 2; q++) {
        ulonglong2 p0 = *(const ulonglong2*)(myP + q * 8);
        ulonglong2 p1 = *(const ulonglong2*)(myP + q * 8 + 4);
        A[q*4+0] = add2(p0.x, cb[q*4+0]);
        A[q*4+1] = add2(p0.y, cb[q*4+1]);
        A[q*4+2] = add2(p1.x, cb[q*4+2]);
        A[q*4+3] = add2(p1.y, cb[q*4+3]);
    }
#pragma unroll
    for (int c = 0; c < 8; c++) {
        float4 a4 = *(const float4*)(myA + (c ^ swz) * 4);   // de-swizzle
        float av[4] = {a4.x, a4.y, a4.z, a4.w};
#pragma unroll
        for (int jj = 0; jj < 4; jj++) {
            u64 adup;
            asm("mov.b64 %0,{%1,%1};" : "=l"(adup) : "f"(av[jj]));
            const u64* wrow = cw + (c*4 + jj) * 8;           // uniform address
#pragma unroll
            for (int p = 0; p < 8; p++)
                asm("fma.rn.f32x2 %0,%1,%2,%0;" : "+l"(A[p]) : "l"(wrow[p]), "l"(adup));
        }
    }
    mlp_tail_and_red(A, v, g, lane);

    // ---- fused finish (canonical threadFenceReduction pattern) ----
    __shared__ unsigned sTicket;
    __syncthreads();                        // all REDs of this block issued
    if (t == 0) {
        __threadfence();                    // release: block's REDs visible gpu-wide
        sTicket = atomicAdd(&g_done, 1u);
    }
    __syncthreads();
    if (sTicket == (unsigned)(n_tiles - 1)) {
        __threadfence();                    // acquire: all other blocks' REDs visible
        float s = 0.0f;
#pragma unroll
        for (int i = 0; i < NSLOT; i++) {
            s += __ldcg(&g_bins[t * NSLOT + i]);
            __stcg(&g_bins[t * NSLOT + i], 0.0f);
        }
        out[t] = s;                         // t in [0,128) == N_GRAPHS_C
        if (t == 0) g_done = 0;
    }
}

// ================= fallback edge kernel (R9 path) =================
__global__ void __launch_bounds__(THREADS) edge_kernel_fb(
    const float* __restrict__ edge_attr,
    const int* __restrict__ ei,
    const int* __restrict__ batch,
    int n_edges) {
    extern __shared__ float smf[];
    float* sRow = smf;
    int*   sSrc = (int*)(smf + TILE * RSTRIDE);

    const int t    = threadIdx.x;
    const int lane = t & 31;
    const int e0   = blockIdx.x * TILE;
    const int e    = e0 + t;
    const bool v   = e < n_edges;

    int src = 0, g = 0;
    if (v) {
        src = __ldg(ei + e);
        g   = __ldg(batch + __ldg(ei + n_edges + e));
    }
    sSrc[t] = src;
    __syncthreads();
    {
#pragma unroll
        for (int r = 0; r < (TILE * 4) / THREADS; r++) {
            int idx = r * THREADS + t;
            int el  = idx >> 2;
            int q   = idx & 3;
            int s   = sSrc[el];
            float4 pv = __ldg((const float4*)g_p + (size_t)s * 4 + q);
            *(float4*)(sRow + el * RSTRIDE + D_EDGE + q * 4) = pv;
        }
        const float4* ga = (const float4*)edge_attr;
        const long long base  = (long long)e0 * (D_EDGE / 4);
        const long long total = (long long)n_edges * (D_EDGE / 4);
#pragma unroll
        for (int r = 0; r < (TILE * (D_EDGE / 4)) / THREADS; r++) {
            int idx = r * THREADS + t;
            float4 w = make_float4(0.f, 0.f, 0.f, 0.f);
            if (base + idx < total) w = __ldg(ga + base + idx);
            *(float4*)(sRow + (idx >> 3) * RSTRIDE + (idx & 7) * 4) = w;
        }
    }
    __syncthreads();

    const float* myRow = sRow + t * RSTRIDE;
    const u64* cw = (const u64*)&c_par.W[0][0];
    const u64* cb = (const u64*)&c_par.B[0];
    u64 A[8];
#pragma unroll
    for (int q = 0; q < 2; q++) {
        ulonglong2 p0 = *(const ulonglong2*)(myRow + D_EDGE + q * 8);
        ulonglong2 p1 = *(const ulonglong2*)(myRow + D_EDGE + q * 8 + 4);
        A[q*4+0] = add2(p0.x, cb[q*4+0]);
        A[q*4+1] = add2(p0.y, cb[q*4+1]);
        A[q*4+2] = add2(p1.x, cb[q*4+2]);
        A[q*4+3] = add2(p1.y, cb[q*4+3]);
    }
#pragma unroll
    for (int c = 0; c < 8; c++) {
        float4 a4 = *(const float4*)(myRow + c * 4);
        float av[4] = {a4.x, a4.y, a4.z, a4.w};
#pragma unroll
        for (int jj = 0; jj < 4; jj++) {
            u64 adup;
            asm("mov.b64 %0,{%1,%1};" : "=l"(adup) : "f"(av[jj]));
            const u64* wrow = cw + (c*4 + jj) * 8;
#pragma unroll
            for (int p = 0; p < 8; p++)
                asm("fma.rn.f32x2 %0,%1,%2,%0;" : "+l"(A[p]) : "l"(wrow[p]), "l"(adup));
        }
    }
    mlp_tail_and_red(A, v, g, lane);
}

// -------- finish (fallback path only) --------
__global__ void finish_kernel(float* __restrict__ out) {
    int g = blockIdx.x;
    int lane = threadIdx.x;
    float s = g_bins[g * NSLOT + lane];
    g_bins[g * NSLOT + lane] = 0.0f;
#pragma unroll
    for (int m = 16; m >= 1; m >>= 1) s += __shfl_xor_sync(0xffffffffu, s, m);
    if (lane == 0) out[g] = s;
}

#define EDGE_SMEM_FB (TILE * RSTRIDE * 4 + TILE * 4)

typedef CUresult (*EncodeFn)(CUtensorMap*, CUtensorMapDataType, cuuint32_t, void*,
                             const cuuint64_t*, const cuuint64_t*, const cuuint32_t*,
                             const cuuint32_t*, CUtensorMapInterleave, CUtensorMapSwizzle,
                             CUtensorMapL2promotion, CUtensorMapFloatOOBfill);

extern "C" void kernel_launch(void* const* d_in, const int* in_sizes, int n_in,
                              void* d_out, int out_size) {
    const float* x         = (const float*)d_in[0];
    const float* edge_attr = (const float*)d_in[1];
    const int*   ei        = (const int*)d_in[2];
    const int*   batch     = (const int*)d_in[3];
    const float* W1        = (const float*)d_in[4];
    const float* b1        = (const float*)d_in[5];
    const float* gamma     = (const float*)d_in[6];
    const float* beta      = (const float*)d_in[7];
    const float* rm        = (const float*)d_in[8];
    const float* rv        = (const float*)d_in[9];
    const float* W2        = (const float*)d_in[10];
    const float* b2        = (const float*)d_in[11];
    float* out = (float*)d_out;

    const int n_nodes = in_sizes[0] / D_NODE;
    const int n_edges = in_sizes[1] / D_EDGE;
    const int n_tiles = (n_edges + TILE - 1) / TILE;

    cudaFuncSetAttribute(edge_kernel_tma, cudaFuncAttributeMaxDynamicSharedMemorySize, EDGE_SMEM_TMA);
    cudaFuncSetAttribute(edge_kernel_fb,  cudaFuncAttributeMaxDynamicSharedMemorySize, EDGE_SMEM_FB);

    // build tensormap via runtime-resolved driver entry point (no -lcuda)
    bool use_tma = false;
    CUtensorMap tmap;
    {
        void* sym = nullptr;
        cudaDriverEntryPointQueryResult qr;
        if (cudaGetDriverEntryPoint("cuTensorMapEncodeTiled", &sym,
                                    cudaEnableDefault, &qr) == cudaSuccess &&
            qr == cudaDriverEntryPointSuccess && sym) {
            EncodeFn enc = (EncodeFn)sym;
            cuuint64_t dims[2]    = {(cuuint64_t)D_EDGE, (cuuint64_t)n_edges};
            cuuint64_t strides[1] = {(cuuint64_t)D_EDGE * sizeof(float)};
            cuuint32_t box[2]     = {(cuuint32_t)D_EDGE, (cuuint32_t)TILE};
            cuuint32_t estr[2]    = {1, 1};
            CUresult r = enc(&tmap, CU_TENSOR_MAP_DATA_TYPE_FLOAT32, 2,
                             (void*)edge_attr, dims, strides, box, estr,
                             CU_TENSOR_MAP_INTERLEAVE_NONE, CU_TENSOR_MAP_SWIZZLE_128B,
                             CU_TENSOR_MAP_L2_PROMOTION_L2_128B,
                             CU_TENSOR_MAP_FLOAT_OOB_FILL_NONE);
            use_tma = (r == CUDA_SUCCESS);
        }
    }

    void *c_addr = nullptr, *g_addr = nullptr;
    cudaGetSymbolAddress(&c_addr, c_par);
    cudaGetSymbolAddress(&g_addr, g_par);

    prep_kernel<<<8, 256>>>(W1, b1, gamma, beta, rm, rv, W2, b2);
    cudaMemcpyAsync(c_addr, g_addr, sizeof(CP), cudaMemcpyDeviceToDevice, 0);
    node_kernel<<<(n_nodes + NT - 1) / NT, NT>>>(x, n_nodes);
    if (use_tma) {
        edge_kernel_tma<<<n_tiles, THREADS, EDGE_SMEM_TMA>>>(tmap, ei, batch, out, n_edges, n_tiles);
    } else {
        edge_kernel_fb<<<n_tiles, THREADS, EDGE_SMEM_FB>>>(edge_attr, ei, batch, n_edges);
        finish_kernel<<<N_GRAPHS_C, NSLOT>>>(out);
    }
}